// round 16
// baseline (speedup 1.0000x reference)
#include <cuda_runtime.h>
#include <cuda_fp16.h>
#include <cstdint>

#define DI __device__ __forceinline__

constexpr int BATCH = 8192, AGENTS = 8, OBSD = 2048, ACTD = 128;
constexpr int IND = 2176, HD = 1024, NTOT = 8192, NAOUT = 128;

__device__ __align__(256) __half g_X  [(size_t)BATCH * IND];
__device__ __align__(256) __half g_Bt1[(size_t)NTOT * IND];
__device__ __align__(256) __half g_Bt2[(size_t)NTOT * HD];
__device__ __align__(256) __half g_Bt3[(size_t)NAOUT * HD];
__device__ __align__(256) __half g_H1 [(size_t)BATCH * NTOT];
__device__ __align__(256) __half g_H2 [(size_t)BATCH * NTOT];

DI uint32_t smem_u32(const void* p) {
    uint32_t a;
    asm("{ .reg .u64 t; cvta.to.shared.u64 t, %1; cvt.u32.u64 %0, t; }" : "=r"(a) : "l"(p));
    return a;
}
#define SWZ(o) ((o) ^ (((o) >> 3) & 0x70))
DI void cp_async16(uint32_t d, const void* s) {
    asm volatile("cp.async.cg.shared.global [%0], [%1], 16;" :: "r"(d), "l"(s) : "memory");
}
DI void cp_commit() { asm volatile("cp.async.commit_group;" ::: "memory"); }
template<int N> DI void cp_wait() {
    asm volatile("cp.async.wait_group %0;" :: "n"(N) : "memory");
}
DI void ldsm4(uint32_t* r, uint32_t a) {
    asm volatile("ldmatrix.sync.aligned.m8n8.x4.shared.b16 {%0,%1,%2,%3}, [%4];"
                 : "=r"(r[0]), "=r"(r[1]), "=r"(r[2]), "=r"(r[3]) : "r"(a));
}
DI void mma16(float* d, const uint32_t* a, const uint32_t* b) {
    asm volatile("mma.sync.aligned.m16n8k16.row.col.f32.f16.f16.f32 "
                 "{%0,%1,%2,%3}, {%4,%5,%6,%7}, {%8,%9}, {%0,%1,%2,%3};"
                 : "+f"(d[0]), "+f"(d[1]), "+f"(d[2]), "+f"(d[3])
                 : "r"(a[0]), "r"(a[1]), "r"(a[2]), "r"(a[3]), "r"(b[0]), "r"(b[1]));
}

// ---- pack X = half([obs | act]) ----
__global__ void k_pack(const float* __restrict__ obs, const float* __restrict__ act,
                       __half* __restrict__ X) {
    int idx = blockIdx.x * blockDim.x + threadIdx.x;
    if (idx >= BATCH * IND / 8) return;
    int e = idx * 8, row = e / IND, col = e % IND;
    const float* src = (col < OBSD) ? obs + (size_t)row * OBSD + col
                                    : act + (size_t)row * ACTD + (col - OBSD);
    float4 v0 = *(const float4*)(src);
    float4 v1 = *(const float4*)(src + 4);
    __half2 h[4];
    h[0] = __floats2half2_rn(v0.x, v0.y);
    h[1] = __floats2half2_rn(v0.z, v0.w);
    h[2] = __floats2half2_rn(v1.x, v1.y);
    h[3] = __floats2half2_rn(v1.z, v1.w);
    *(uint4*)(X + e) = *(uint4*)h;
}

// ---- W[a][K][N] -> Bt[a*N+n][K] (half), optional action-mask fold ----
__global__ void k_transpose(const float* __restrict__ W, __half* __restrict__ Bt,
                            int K, int N, int doMask) {
    __shared__ float t[32][33];
    int a = blockIdx.z;
    const float* Wa = W + (size_t)a * K * N;
    __half* Bta = Bt + (size_t)a * N * K;
    int k0 = blockIdx.x << 5, n0 = blockIdx.y << 5;
    int tx = threadIdx.x, ty = threadIdx.y;
    #pragma unroll
    for (int i = 0; i < 4; i++) {
        int kk = ty + i * 8, n = n0 + tx;
        t[kk][tx] = (n < N) ? Wa[(size_t)(k0 + kk) * N + n] : 0.f;
    }
    __syncthreads();
    #pragma unroll
    for (int i = 0; i < 4; i++) {
        int nn = ty + i * 8, n = n0 + nn;
        if (n >= N) continue;
        int k = k0 + tx;
        float v = t[tx][nn];
        if (doMask && k >= OBSD && (((k - OBSD) >> 4) == a)) v = 0.f;
        Bta[(size_t)n * K + k] = __float2half_rn(v);
    }
}

// ---- mma.sync fp16 GEMM: out = act(A[:, koff:koff+K] @ Bt^T + bias) ----
// NST=3, one k-tile per barrier; 2 CTAs/SM overlap each other's bubbles.
template<int BM, int BN, int WM, int WN, int MINCTA, bool RELU, typename OutT>
__global__ __launch_bounds__((BM / WM) * (BN / WN) * 32, MINCTA)
void gemm_f16(const __half* __restrict__ A, int lda,
              const __half* __restrict__ Bt, int ldb, int K,
              const float* __restrict__ bias,
              OutT* __restrict__ out, int ldout,
              int nPerAgent, int aKStride)
{
    constexpr int WR = BM / WM, WC = BN / WN, THREADS = WR * WC * 32;
    constexpr int MF = WM / 16, NF = WN / 8, NP = NF / 2;
    constexpr int NST = 3;
    constexpr int STAGE = (BM + BN) * 128;

    extern __shared__ __align__(1024) unsigned char smem[];
    const uint32_t sbase = smem_u32(smem);
    const int tid = threadIdx.x, warp = tid >> 5, lane = tid & 31;
    const int wm = warp / WC, wn = warp % WC;
    const int mbase = blockIdx.y * BM, nbase = blockIdx.x * BN;
    const int agent = nbase / nPerAgent, koff = agent * aKStride;
    const int KT = K / 64;

    const __half* Ag = A + (size_t)mbase * lda + koff;
    const __half* Bg = Bt + (size_t)nbase * ldb;

    const int g = lane >> 3, lr = lane & 7;
    uint32_t aOff[MF], bOff[NP];
    #pragma unroll
    for (int i = 0; i < MF; i++) {
        int row = wm * WM + i * 16 + (g & 1) * 8 + lr;
        aOff[i] = SWZ((uint32_t)(row * 128 + (g >> 1) * 16));
    }
    #pragma unroll
    for (int p = 0; p < NP; p++) {
        int row = wn * WN + (p * 2 + (g >> 1)) * 8 + lr;
        bOff[p] = (uint32_t)(BM * 128) + SWZ((uint32_t)(row * 128 + (g & 1) * 16));
    }

    auto load_stage = [&](int kt) {
        const uint32_t sS = sbase + (kt % NST) * STAGE;
        const __half* Ak = Ag + kt * 64;
        #pragma unroll
        for (int i = tid; i < BM * 8; i += THREADS) {
            int r = i >> 3, c = i & 7;
            cp_async16(sS + SWZ((uint32_t)(r * 128 + c * 16)), Ak + (size_t)r * lda + c * 8);
        }
        const __half* Bk = Bg + kt * 64;
        #pragma unroll
        for (int i = tid; i < BN * 8; i += THREADS) {
            int r = i >> 3, c = i & 7;
            cp_async16(sS + BM * 128 + SWZ((uint32_t)(r * 128 + c * 16)),
                       Bk + (size_t)r * ldb + c * 8);
        }
        cp_commit();
    };

    float acc[MF][NF][4];
    #pragma unroll
    for (int i = 0; i < MF; i++)
        #pragma unroll
        for (int j = 0; j < NF; j++)
            #pragma unroll
            for (int e = 0; e < 4; e++) acc[i][j][e] = 0.f;

    auto compute_tile = [&](int kt) {
        const uint32_t sS = sbase + (kt % NST) * STAGE;
        #pragma unroll
        for (int kk = 0; kk < 4; kk++) {
            const uint32_t kx = (uint32_t)(kk * 32);
            uint32_t a[MF][4], b[NP][4];
            #pragma unroll
            for (int i = 0; i < MF; i++) ldsm4(a[i], sS + (aOff[i] ^ kx));
            #pragma unroll
            for (int p = 0; p < NP; p++) ldsm4(b[p], sS + (bOff[p] ^ kx));
            #pragma unroll
            for (int i = 0; i < MF; i++)
                #pragma unroll
                for (int p = 0; p < NP; p++) {
                    mma16(acc[i][2 * p],     a[i], &b[p][0]);
                    mma16(acc[i][2 * p + 1], a[i], &b[p][2]);
                }
        }
    };

    load_stage(0);
    if (KT > 1) load_stage(1);

    for (int kt = 0; kt < KT; kt++) {
        if (kt < KT - 2) cp_wait<1>();
        else             cp_wait<0>();
        __syncthreads();
        if (kt + 2 < KT) load_stage(kt + 2);
        compute_tile(kt);
    }

    // epilogue: +bias(fp32), relu, store
    const int r0 = lane >> 2, cb = 2 * (lane & 3);
    #pragma unroll
    for (int i = 0; i < MF; i++) {
        const int grow = mbase + wm * WM + i * 16 + r0;
        #pragma unroll
        for (int j = 0; j < NF; j++) {
            const int gcol = nbase + wn * WN + j * 8 + cb;
            const float2 bj = *(const float2*)(bias + gcol);
            float v0 = acc[i][j][0] + bj.x, v1 = acc[i][j][1] + bj.y;
            float v2 = acc[i][j][2] + bj.x, v3 = acc[i][j][3] + bj.y;
            if (RELU) { v0 = fmaxf(v0, 0.f); v1 = fmaxf(v1, 0.f);
                        v2 = fmaxf(v2, 0.f); v3 = fmaxf(v3, 0.f); }
            if constexpr (sizeof(OutT) == 2) {
                *(__half2*)((__half*)out + (size_t)grow * ldout + gcol) =
                    __floats2half2_rn(v0, v1);
                *(__half2*)((__half*)out + (size_t)(grow + 8) * ldout + gcol) =
                    __floats2half2_rn(v2, v3);
            } else {
                *(float2*)((float*)out + (size_t)grow * ldout + gcol)       = make_float2(v0, v1);
                *(float2*)((float*)out + (size_t)(grow + 8) * ldout + gcol) = make_float2(v2, v3);
            }
        }
    }
}

extern "C" void kernel_launch(void* const* d_in, const int* in_sizes, int n_in,
                              void* d_out, int out_size) {
    (void)in_sizes; (void)n_in; (void)out_size;
    const float* obs = (const float*)d_in[0];
    const float* act = (const float*)d_in[1];
    const float* W1  = (const float*)d_in[2];
    const float* b1  = (const float*)d_in[3];
    const float* W2  = (const float*)d_in[4];
    const float* b2  = (const float*)d_in[5];
    const float* W3  = (const float*)d_in[6];
    const float* b3  = (const float*)d_in[7];
    float* out = (float*)d_out;

    void *pX, *pBt1, *pBt2, *pBt3, *pH1, *pH2;
    cudaGetSymbolAddress(&pX,  g_X);
    cudaGetSymbolAddress(&pBt1, g_Bt1);
    cudaGetSymbolAddress(&pBt2, g_Bt2);
    cudaGetSymbolAddress(&pBt3, g_Bt3);
    cudaGetSymbolAddress(&pH1, g_H1);
    cudaGetSymbolAddress(&pH2, g_H2);

    constexpr int SM_BIG = 3 * (128 + 128) * 128;   // 96 KB -> 2 CTAs/SM
    constexpr int SM_L3  = 3 * (128 + 16) * 128;    // 54 KB -> 2+ CTAs/SM
    cudaFuncSetAttribute((const void*)gemm_f16<128, 128, 64, 64, 2, true,  __half>,
                         cudaFuncAttributeMaxDynamicSharedMemorySize, SM_BIG);
    cudaFuncSetAttribute((const void*)gemm_f16<128, 16, 32, 16, 2, false, float>,
                         cudaFuncAttributeMaxDynamicSharedMemorySize, SM_L3);

    // Launch order keeps GEMM1 as the 4th launch (ncu capture window).
    k_pack<<<(BATCH * IND / 8 + 255) / 256, 256>>>(obs, act, (__half*)pX);                        // 1
    k_transpose<<<dim3(IND / 32, HD / 32, AGENTS), dim3(32, 8)>>>(W1, (__half*)pBt1, IND, HD, 1); // 2
    k_transpose<<<dim3(HD / 32, HD / 32, AGENTS), dim3(32, 8)>>>(W2, (__half*)pBt2, HD, HD, 0);   // 3

    // 4: L1: H1 = relu(X @ Bt1^T + b1)   M=8192 N=8192 K=2176
    gemm_f16<128, 128, 64, 64, 2, true, __half>
        <<<dim3(NTOT / 128, BATCH / 128), 128, SM_BIG>>>(
        (const __half*)pX, IND, (const __half*)pBt1, IND, IND, b1,
        (__half*)pH1, NTOT, 1024, 0);

    // 5: L2: H2 = relu(H1[:, a*1024:+1024] @ Bt2^T + b2)
    gemm_f16<128, 128, 64, 64, 2, true, __half>
        <<<dim3(NTOT / 128, BATCH / 128), 128, SM_BIG>>>(
        (const __half*)pH1, NTOT, (const __half*)pBt2, HD, HD, b2,
        (__half*)pH2, NTOT, 1024, 1024);

    // 6: W3 transpose
    k_transpose<<<dim3(HD / 32, 1, AGENTS), dim3(32, 8)>>>(W3, (__half*)pBt3, HD, 16, 0);

    // 7: L3: out = H2[:, a*1024:+1024] @ Bt3^T + b3
    gemm_f16<128, 16, 32, 16, 2, false, float>
        <<<dim3(NAOUT / 16, BATCH / 128), 128, SM_L3>>>(
        (const __half*)pH2, NTOT, (const __half*)pBt3, HD, HD, b3,
        out, NAOUT, 16, 1024);
}